// round 6
// baseline (speedup 1.0000x reference)
#include <cuda_runtime.h>

#define T_STEPS 240
#define H       25
#define BLK     128
#define WPB     (BLK / 32)

typedef unsigned long long u64;

// ---------------------------------------------------------------------------
// Packed f32x2 helpers (Blackwell)
// ---------------------------------------------------------------------------
__device__ __forceinline__ u64 pack2(float lo, float hi) {
    u64 r;
    asm("mov.b64 %0, {%1, %2};" : "=l"(r) : "f"(lo), "f"(hi));
    return r;
}
__device__ __forceinline__ float unpack_sum(u64 v) {
    float lo, hi;
    asm("mov.b64 {%0, %1}, %2;" : "=f"(lo), "=f"(hi) : "l"(v));
    return lo + hi;
}
#define FFMA2(acc, h, w) \
    asm("fma.rn.f32x2 %0, %1, %2, %0;" : "+l"(acc) : "l"(h), "l"(w))

// MUFU-based activations (~1e-7 rel err; exact at saturation).
__device__ __forceinline__ float sigmoid_f(float x) {
    float e = __expf(-x);
    return __fdividef(1.f, 1.f + e);
}
__device__ __forceinline__ float tanh_f(float x) {
    float e = __expf(-2.f * x);
    return __fdividef(2.f, 1.f + e) - 1.f;
}

// Packed-k indices 0..12 (k pairs (0,1)..(24,25); k=25 padded to 0)
#define R13(M) M(0) M(1) M(2) M(3) M(4) M(5) M(6) M(7) M(8) M(9) M(10) M(11) M(12)

#define DECL_WP(Q) u64 wi##Q, wf##Q, wg##Q, wo##Q;

#define LOAD_WP(Q) {                                                          \
    const int k0 = 2 * (Q), k1 = 2 * (Q) + 1;                                 \
    float a, b;                                                               \
    a = (lv && k0 < H) ? __ldg(&W_hh[(0 * H + jc) * H + k0]) : 0.f;           \
    b = (lv && k1 < H) ? __ldg(&W_hh[(0 * H + jc) * H + k1]) : 0.f;           \
    wi##Q = pack2(a, b);                                                      \
    a = (lv && k0 < H) ? __ldg(&W_hh[(1 * H + jc) * H + k0]) : 0.f;           \
    b = (lv && k1 < H) ? __ldg(&W_hh[(1 * H + jc) * H + k1]) : 0.f;           \
    wf##Q = pack2(a, b);                                                      \
    a = (lv && k0 < H) ? __ldg(&W_hh[(2 * H + jc) * H + k0]) : 0.f;           \
    b = (lv && k1 < H) ? __ldg(&W_hh[(2 * H + jc) * H + k1]) : 0.f;           \
    wg##Q = pack2(a, b);                                                      \
    a = (lv && k0 < H) ? __ldg(&W_hh[(3 * H + jc) * H + k0]) : 0.f;           \
    b = (lv && k1 < H) ? __ldg(&W_hh[(3 * H + jc) * H + k1]) : 0.f;           \
    wo##Q = pack2(a, b);                                                      \
}

// 4 packed-gate FMAs for one packed h pair. S = batch slot, P = pair index.
#define GP(S, V, P)                                                           \
    FFMA2(ai##S, (V), wi##P); FFMA2(af##S, (V), wf##P);                       \
    FFMA2(ag##S, (V), wg##P); FFMA2(ao##S, (V), wo##P);

// Full 26-wide (13-pair) MAC for batch slot S from broadcast buffer BASE.
// BASE is 16B-aligned (28-float = 112B stride).
#define MACS(S, BASE) {                                                       \
    ulonglong2 A0 = *reinterpret_cast<const ulonglong2*>((BASE) + 0);         \
    ulonglong2 A1 = *reinterpret_cast<const ulonglong2*>((BASE) + 4);         \
    ulonglong2 A2 = *reinterpret_cast<const ulonglong2*>((BASE) + 8);         \
    ulonglong2 A3 = *reinterpret_cast<const ulonglong2*>((BASE) + 12);        \
    ulonglong2 A4 = *reinterpret_cast<const ulonglong2*>((BASE) + 16);        \
    ulonglong2 A5 = *reinterpret_cast<const ulonglong2*>((BASE) + 20);        \
    u64        A6 = *reinterpret_cast<const u64*>((BASE) + 24);               \
    GP(S, A0.x, 0)  GP(S, A0.y, 1)  GP(S, A1.x, 2)  GP(S, A1.y, 3)            \
    GP(S, A2.x, 4)  GP(S, A2.y, 5)  GP(S, A3.x, 6)  GP(S, A3.y, 7)            \
    GP(S, A4.x, 8)  GP(S, A4.y, 9)  GP(S, A5.x, 10) GP(S, A5.y, 11)           \
    GP(S, A6, 12) }

// Gate nonlinearity + state update for batch slot S.
#define ACT(S, XV) {                                                          \
    float vi = unpack_sum(ai##S) + fmaf((XV), wih_i, bias_i);                 \
    float vf = unpack_sum(af##S) + fmaf((XV), wih_f, bias_f);                 \
    float vg = unpack_sum(ag##S) + fmaf((XV), wih_g, bias_g);                 \
    float vo = unpack_sum(ao##S) + fmaf((XV), wih_o, bias_o);                 \
    float ig = sigmoid_f(vi), fg = sigmoid_f(vf);                             \
    float gg = tanh_f(vg),    og = sigmoid_f(vo);                             \
    c##S = fmaf(fg, c##S, ig * gg);                                           \
    h##S = og * tanh_f(c##S);                                                 \
}

// One timestep for 4 batches. BP = this step's parity buffer base
// (4 batches x 28 floats). Double-buffered by caller; one syncwarp/step.
#define LSTM_STEP(BP, X0, X1, X2, X3) do {                                    \
    if (lane < 28) {                                                          \
        (BP)[lane]      = h0; (BP)[28 + lane] = h1;                           \
        (BP)[56 + lane] = h2; (BP)[84 + lane] = h3;                           \
    }                                                                         \
    __syncwarp();                                                             \
    u64 ai0 = 0, af0 = 0, ag0 = 0, ao0 = 0;                                   \
    u64 ai1 = 0, af1 = 0, ag1 = 0, ao1 = 0;                                   \
    u64 ai2 = 0, af2 = 0, ag2 = 0, ao2 = 0;                                   \
    u64 ai3 = 0, af3 = 0, ag3 = 0, ao3 = 0;                                   \
    MACS(0, (BP))      MACS(1, (BP) + 28)                                     \
    MACS(2, (BP) + 56) MACS(3, (BP) + 84)                                     \
    ACT(0, (X0)) ACT(1, (X1)) ACT(2, (X2)) ACT(3, (X3))                       \
} while (0)

__global__ void __launch_bounds__(BLK) lstm_kernel(
    const float* __restrict__ x,      // [B, T, 1]
    const float* __restrict__ W_ih,   // [4H, 1]
    const float* __restrict__ W_hh,   // [4H, H]
    const float* __restrict__ b_ih,   // [4H]
    const float* __restrict__ b_hh,   // [4H]
    const float* __restrict__ W_fc,   // [2, H]
    const float* __restrict__ b_fc,   // [2]
    float* __restrict__ out,          // [B, 2]
    int B)
{
    // h-broadcast buffers: [warp][parity][batch slot][28 units]; 28-float
    // stride = 112 B (16B-aligned). Lanes 25-27 write exact zeros (their
    // weights/biases are zero so their h stays 0 forever).
    __shared__ __align__(16) float hb[WPB][2][4][28];

    const int lane = threadIdx.x & 31;
    const int wIn  = threadIdx.x >> 5;
    const int warpGlobal = (blockIdx.x * BLK + threadIdx.x) >> 5;

    const bool lv = (lane < H);
    const int  jc = lv ? lane : (H - 1);

    int b0 = 4 * warpGlobal + 0;
    int b1 = 4 * warpGlobal + 1;
    int b2 = 4 * warpGlobal + 2;
    int b3 = 4 * warpGlobal + 3;
    const bool v0 = (b0 < B), v1 = (b1 < B), v2 = (b2 < B), v3 = (b3 < B);
    if (!v0) b0 = B - 1;
    if (!v1) b1 = B - 1;
    if (!v2) b2 = B - 1;
    if (!v3) b3 = B - 1;

    // K-packed recurrent weights: 52 named u64 SSA values (cannot be demoted).
    R13(DECL_WP)
    R13(LOAD_WP)

    const float wih_i = lv ? __ldg(&W_ih[0 * H + jc]) : 0.f;
    const float wih_f = lv ? __ldg(&W_ih[1 * H + jc]) : 0.f;
    const float wih_g = lv ? __ldg(&W_ih[2 * H + jc]) : 0.f;
    const float wih_o = lv ? __ldg(&W_ih[3 * H + jc]) : 0.f;
    const float bias_i = lv ? __ldg(&b_ih[0 * H + jc]) + __ldg(&b_hh[0 * H + jc]) : 0.f;
    const float bias_f = lv ? __ldg(&b_ih[1 * H + jc]) + __ldg(&b_hh[1 * H + jc]) : 0.f;
    const float bias_g = lv ? __ldg(&b_ih[2 * H + jc]) + __ldg(&b_hh[2 * H + jc]) : 0.f;
    const float bias_o = lv ? __ldg(&b_ih[3 * H + jc]) + __ldg(&b_hh[3 * H + jc]) : 0.f;

    float* bufA = &hb[wIn][0][0][0];
    float* bufB = &hb[wIn][1][0][0];

    float h0 = 0.f, c0 = 0.f, h1 = 0.f, c1 = 0.f;
    float h2 = 0.f, c2 = 0.f, h3 = 0.f, c3 = 0.f;

    const float4* xq0p = reinterpret_cast<const float4*>(x + (size_t)b0 * T_STEPS);
    const float4* xq1p = reinterpret_cast<const float4*>(x + (size_t)b1 * T_STEPS);
    const float4* xq2p = reinterpret_cast<const float4*>(x + (size_t)b2 * T_STEPS);
    const float4* xq3p = reinterpret_cast<const float4*>(x + (size_t)b3 * T_STEPS);

#pragma unroll 1
    for (int t4 = 0; t4 < T_STEPS / 4; t4++) {
        float4 xq0 = __ldg(xq0p + t4);   // warp-uniform broadcast loads
        float4 xq1 = __ldg(xq1p + t4);
        float4 xq2 = __ldg(xq2p + t4);
        float4 xq3 = __ldg(xq3p + t4);
        LSTM_STEP(bufA, xq0.x, xq1.x, xq2.x, xq3.x);
        LSTM_STEP(bufB, xq0.y, xq1.y, xq2.y, xq3.y);
        LSTM_STEP(bufA, xq0.z, xq1.z, xq2.z, xq3.z);
        LSTM_STEP(bufB, xq0.w, xq1.w, xq2.w, xq3.w);
    }

    // FC head: warp-reduce h . W_fc^T (idle lanes contribute h=0)
    const float wfc0 = lv ? __ldg(&W_fc[jc])     : 0.f;
    const float wfc1 = lv ? __ldg(&W_fc[H + jc]) : 0.f;
    float s00 = h0 * wfc0, s01 = h0 * wfc1;
    float s10 = h1 * wfc0, s11 = h1 * wfc1;
    float s20 = h2 * wfc0, s21 = h2 * wfc1;
    float s30 = h3 * wfc0, s31 = h3 * wfc1;
#pragma unroll
    for (int off = 16; off > 0; off >>= 1) {
        s00 += __shfl_xor_sync(0xffffffffu, s00, off);
        s01 += __shfl_xor_sync(0xffffffffu, s01, off);
        s10 += __shfl_xor_sync(0xffffffffu, s10, off);
        s11 += __shfl_xor_sync(0xffffffffu, s11, off);
        s20 += __shfl_xor_sync(0xffffffffu, s20, off);
        s21 += __shfl_xor_sync(0xffffffffu, s21, off);
        s30 += __shfl_xor_sync(0xffffffffu, s30, off);
        s31 += __shfl_xor_sync(0xffffffffu, s31, off);
    }
    if (lane == 0) {
        const float bf0 = __ldg(&b_fc[0]), bf1 = __ldg(&b_fc[1]);
        if (v0) { out[(size_t)b0 * 2 + 0] = s00 + bf0; out[(size_t)b0 * 2 + 1] = s01 + bf1; }
        if (v1) { out[(size_t)b1 * 2 + 0] = s10 + bf0; out[(size_t)b1 * 2 + 1] = s11 + bf1; }
        if (v2) { out[(size_t)b2 * 2 + 0] = s20 + bf0; out[(size_t)b2 * 2 + 1] = s21 + bf1; }
        if (v3) { out[(size_t)b3 * 2 + 0] = s30 + bf0; out[(size_t)b3 * 2 + 1] = s31 + bf1; }
    }
}

extern "C" void kernel_launch(void* const* d_in, const int* in_sizes, int n_in,
                              void* d_out, int out_size) {
    const float* x    = (const float*)d_in[0];
    const float* W_ih = (const float*)d_in[1];
    const float* W_hh = (const float*)d_in[2];
    const float* b_ih = (const float*)d_in[3];
    const float* b_hh = (const float*)d_in[4];
    const float* W_fc = (const float*)d_in[5];
    const float* b_fc = (const float*)d_in[6];

    int B = in_sizes[0] / T_STEPS;          // x is [B, T, 1]
    int warpsNeeded = (B + 3) / 4;          // 4 batches per warp
    int blocks      = (warpsNeeded * 32 + BLK - 1) / BLK;

    lstm_kernel<<<blocks, BLK>>>(x, W_ih, W_hh, b_ih, b_hh, W_fc, b_fc,
                                 (float*)d_out, B);
}

// round 8
// speedup vs baseline: 1.2639x; 1.2639x over previous
#include <cuda_runtime.h>

#define T_STEPS 240
#define H       25
#define BLK     128
#define WPB     (BLK / 32)

typedef unsigned long long u64;

// ---------------------------------------------------------------------------
// Packed f32x2 helpers (Blackwell)
// ---------------------------------------------------------------------------
__device__ __forceinline__ u64 pack2(float lo, float hi) {
    u64 r;
    asm("mov.b64 %0, {%1, %2};" : "=l"(r) : "f"(lo), "f"(hi));
    return r;
}
__device__ __forceinline__ float unpack_sum(u64 v) {
    float lo, hi;
    asm("mov.b64 {%0, %1}, %2;" : "=f"(lo), "=f"(hi) : "l"(v));
    return lo + hi;
}
#define FFMA2(acc, h, w) \
    asm("fma.rn.f32x2 %0, %1, %2, %0;" : "+l"(acc) : "l"(h), "l"(w))

// ---------------------------------------------------------------------------
// Single-MUFU activations via hardware tanh (sm_75+): tanh.approx.f32.
// sigmoid(x) = 0.5*tanh(x/2) + 0.5  -> 1 MUFU + 2 fma-ops.
// ---------------------------------------------------------------------------
__device__ __forceinline__ float tanh_ap(float x) {
    float y;
    asm("tanh.approx.f32 %0, %1;" : "=f"(y) : "f"(x));
    return y;
}
__device__ __forceinline__ float sigmoid_f(float x) {
    return fmaf(tanh_ap(0.5f * x), 0.5f, 0.5f);
}
__device__ __forceinline__ float tanh_f(float x) { return tanh_ap(x); }

// Packed-k indices 0..12 (k pairs (0,1)..(24,25); k=25 padded to 0)
#define R13(M) M(0) M(1) M(2) M(3) M(4) M(5) M(6) M(7) M(8) M(9) M(10) M(11) M(12)

#define DECL_WP(Q) u64 wi##Q, wf##Q, wg##Q, wo##Q;

#define LOAD_WP(Q) {                                                          \
    const int k0 = 2 * (Q), k1 = 2 * (Q) + 1;                                 \
    float a, b;                                                               \
    a = (lv && k0 < H) ? __ldg(&W_hh[(0 * H + jc) * H + k0]) : 0.f;           \
    b = (lv && k1 < H) ? __ldg(&W_hh[(0 * H + jc) * H + k1]) : 0.f;           \
    wi##Q = pack2(a, b);                                                      \
    a = (lv && k0 < H) ? __ldg(&W_hh[(1 * H + jc) * H + k0]) : 0.f;           \
    b = (lv && k1 < H) ? __ldg(&W_hh[(1 * H + jc) * H + k1]) : 0.f;           \
    wf##Q = pack2(a, b);                                                      \
    a = (lv && k0 < H) ? __ldg(&W_hh[(2 * H + jc) * H + k0]) : 0.f;           \
    b = (lv && k1 < H) ? __ldg(&W_hh[(2 * H + jc) * H + k1]) : 0.f;           \
    wg##Q = pack2(a, b);                                                      \
    a = (lv && k0 < H) ? __ldg(&W_hh[(3 * H + jc) * H + k0]) : 0.f;           \
    b = (lv && k1 < H) ? __ldg(&W_hh[(3 * H + jc) * H + k1]) : 0.f;           \
    wo##Q = pack2(a, b);                                                      \
}

// 4 packed-gate FMAs for one packed h pair. S = batch (0/1), P = pair index.
#define GP(S, V, P)                                                           \
    FFMA2(ai##S, (V), wi##P); FFMA2(af##S, (V), wf##P);                       \
    FFMA2(ag##S, (V), wg##P); FFMA2(ao##S, (V), wo##P);

// One LSTM timestep for both batches. B0/B1 = this step's h-broadcast buffers
// (parity double-buffered by caller). h in smem as 28 scalars -> packed pairs
// read via LDS.128 at warp-uniform (broadcast) addresses.
#define LSTM_STEP(B0, B1, XV0, XV1) do {                                      \
    if (lane < 28) { (B0)[lane] = h0; (B1)[lane] = h1; }                      \
    __syncwarp();                                                             \
    u64 ai0 = 0, af0 = 0, ag0 = 0, ao0 = 0;                                   \
    u64 ai1 = 0, af1 = 0, ag1 = 0, ao1 = 0;                                   \
    { ulonglong2 A = *reinterpret_cast<const ulonglong2*>((B0) + 0);          \
      ulonglong2 C = *reinterpret_cast<const ulonglong2*>((B1) + 0);          \
      GP(0, A.x, 0) GP(0, A.y, 1) GP(1, C.x, 0) GP(1, C.y, 1) }               \
    { ulonglong2 A = *reinterpret_cast<const ulonglong2*>((B0) + 4);          \
      ulonglong2 C = *reinterpret_cast<const ulonglong2*>((B1) + 4);          \
      GP(0, A.x, 2) GP(0, A.y, 3) GP(1, C.x, 2) GP(1, C.y, 3) }               \
    { ulonglong2 A = *reinterpret_cast<const ulonglong2*>((B0) + 8);          \
      ulonglong2 C = *reinterpret_cast<const ulonglong2*>((B1) + 8);          \
      GP(0, A.x, 4) GP(0, A.y, 5) GP(1, C.x, 4) GP(1, C.y, 5) }               \
    { ulonglong2 A = *reinterpret_cast<const ulonglong2*>((B0) + 12);         \
      ulonglong2 C = *reinterpret_cast<const ulonglong2*>((B1) + 12);         \
      GP(0, A.x, 6) GP(0, A.y, 7) GP(1, C.x, 6) GP(1, C.y, 7) }               \
    { ulonglong2 A = *reinterpret_cast<const ulonglong2*>((B0) + 16);         \
      ulonglong2 C = *reinterpret_cast<const ulonglong2*>((B1) + 16);         \
      GP(0, A.x, 8) GP(0, A.y, 9) GP(1, C.x, 8) GP(1, C.y, 9) }               \
    { ulonglong2 A = *reinterpret_cast<const ulonglong2*>((B0) + 20);         \
      ulonglong2 C = *reinterpret_cast<const ulonglong2*>((B1) + 20);         \
      GP(0, A.x, 10) GP(0, A.y, 11) GP(1, C.x, 10) GP(1, C.y, 11) }           \
    { u64 A = *reinterpret_cast<const u64*>((B0) + 24);                       \
      u64 C = *reinterpret_cast<const u64*>((B1) + 24);                       \
      GP(0, A, 12) GP(1, C, 12) }                                             \
    float vi0 = unpack_sum(ai0) + fmaf((XV0), wih_i, bias_i);                 \
    float vf0 = unpack_sum(af0) + fmaf((XV0), wih_f, bias_f);                 \
    float vg0 = unpack_sum(ag0) + fmaf((XV0), wih_g, bias_g);                 \
    float vo0 = unpack_sum(ao0) + fmaf((XV0), wih_o, bias_o);                 \
    float vi1 = unpack_sum(ai1) + fmaf((XV1), wih_i, bias_i);                 \
    float vf1 = unpack_sum(af1) + fmaf((XV1), wih_f, bias_f);                 \
    float vg1 = unpack_sum(ag1) + fmaf((XV1), wih_g, bias_g);                 \
    float vo1 = unpack_sum(ao1) + fmaf((XV1), wih_o, bias_o);                 \
    float ig = sigmoid_f(vi0), fg = sigmoid_f(vf0);                           \
    float gg = tanh_f(vg0),    og = sigmoid_f(vo0);                           \
    c0 = fmaf(fg, c0, ig * gg);  h0 = og * tanh_f(c0);                        \
    ig = sigmoid_f(vi1); fg = sigmoid_f(vf1);                                 \
    gg = tanh_f(vg1);    og = sigmoid_f(vo1);                                 \
    c1 = fmaf(fg, c1, ig * gg);  h1 = og * tanh_f(c1);                        \
} while (0)

__global__ void __launch_bounds__(BLK) lstm_kernel(
    const float* __restrict__ x,      // [B, T, 1]
    const float* __restrict__ W_ih,   // [4H, 1]
    const float* __restrict__ W_hh,   // [4H, H]
    const float* __restrict__ b_ih,   // [4H]
    const float* __restrict__ b_hh,   // [4H]
    const float* __restrict__ W_fc,   // [2, H]
    const float* __restrict__ b_fc,   // [2]
    float* __restrict__ out,          // [B, 2]
    int B)
{
    // h-broadcast buffers: [warp][parity][batch][28 units] (pads written as 0
    // by lanes 25-27, whose zero weights/biases keep their h exactly 0).
    __shared__ __align__(16) float hb[WPB][2][2][28];

    const int lane = threadIdx.x & 31;
    const int wIn  = threadIdx.x >> 5;
    const int warpGlobal = (blockIdx.x * BLK + threadIdx.x) >> 5;

    const bool lv = (lane < H);
    const int  jc = lv ? lane : (H - 1);

    int b0 = 2 * warpGlobal;
    int b1 = 2 * warpGlobal + 1;
    const bool v0 = (b0 < B), v1 = (b1 < B);
    if (!v0) b0 = B - 1;
    if (!v1) b1 = B - 1;

    // K-packed recurrent weights: 52 named u64 SSA values (cannot be demoted).
    R13(DECL_WP)
    R13(LOAD_WP)

    const float wih_i = lv ? __ldg(&W_ih[0 * H + jc]) : 0.f;
    const float wih_f = lv ? __ldg(&W_ih[1 * H + jc]) : 0.f;
    const float wih_g = lv ? __ldg(&W_ih[2 * H + jc]) : 0.f;
    const float wih_o = lv ? __ldg(&W_ih[3 * H + jc]) : 0.f;
    const float bias_i = lv ? __ldg(&b_ih[0 * H + jc]) + __ldg(&b_hh[0 * H + jc]) : 0.f;
    const float bias_f = lv ? __ldg(&b_ih[1 * H + jc]) + __ldg(&b_hh[1 * H + jc]) : 0.f;
    const float bias_g = lv ? __ldg(&b_ih[2 * H + jc]) + __ldg(&b_hh[2 * H + jc]) : 0.f;
    const float bias_o = lv ? __ldg(&b_ih[3 * H + jc]) + __ldg(&b_hh[3 * H + jc]) : 0.f;

    float* bA0 = &hb[wIn][0][0][0];
    float* bA1 = &hb[wIn][0][1][0];
    float* bB0 = &hb[wIn][1][0][0];
    float* bB1 = &hb[wIn][1][1][0];

    float h0 = 0.f, c0 = 0.f, h1 = 0.f, c1 = 0.f;

    const float4* xq0p = reinterpret_cast<const float4*>(x + (size_t)b0 * T_STEPS);
    const float4* xq1p = reinterpret_cast<const float4*>(x + (size_t)b1 * T_STEPS);

#pragma unroll 1
    for (int t4 = 0; t4 < T_STEPS / 4; t4++) {
        float4 xq0 = __ldg(xq0p + t4);   // warp-uniform broadcast loads
        float4 xq1 = __ldg(xq1p + t4);
        LSTM_STEP(bA0, bA1, xq0.x, xq1.x);
        LSTM_STEP(bB0, bB1, xq0.y, xq1.y);
        LSTM_STEP(bA0, bA1, xq0.z, xq1.z);
        LSTM_STEP(bB0, bB1, xq0.w, xq1.w);
    }

    // FC head: warp-reduce h . W_fc^T (idle lanes contribute h=0)
    const float wfc0 = lv ? __ldg(&W_fc[jc])     : 0.f;
    const float wfc1 = lv ? __ldg(&W_fc[H + jc]) : 0.f;
    float s00 = h0 * wfc0, s01 = h0 * wfc1;
    float s10 = h1 * wfc0, s11 = h1 * wfc1;
#pragma unroll
    for (int off = 16; off > 0; off >>= 1) {
        s00 += __shfl_xor_sync(0xffffffffu, s00, off);
        s01 += __shfl_xor_sync(0xffffffffu, s01, off);
        s10 += __shfl_xor_sync(0xffffffffu, s10, off);
        s11 += __shfl_xor_sync(0xffffffffu, s11, off);
    }
    if (lane == 0) {
        const float bf0 = __ldg(&b_fc[0]), bf1 = __ldg(&b_fc[1]);
        if (v0) {
            out[(size_t)b0 * 2 + 0] = s00 + bf0;
            out[(size_t)b0 * 2 + 1] = s01 + bf1;
        }
        if (v1) {
            out[(size_t)b1 * 2 + 0] = s10 + bf0;
            out[(size_t)b1 * 2 + 1] = s11 + bf1;
        }
    }
}

extern "C" void kernel_launch(void* const* d_in, const int* in_sizes, int n_in,
                              void* d_out, int out_size) {
    const float* x    = (const float*)d_in[0];
    const float* W_ih = (const float*)d_in[1];
    const float* W_hh = (const float*)d_in[2];
    const float* b_ih = (const float*)d_in[3];
    const float* b_hh = (const float*)d_in[4];
    const float* W_fc = (const float*)d_in[5];
    const float* b_fc = (const float*)d_in[6];

    int B = in_sizes[0] / T_STEPS;          // x is [B, T, 1]
    int warpsNeeded = (B + 1) / 2;          // 2 batches per warp
    int blocks      = (warpsNeeded * 32 + BLK - 1) / BLK;

    lstm_kernel<<<blocks, BLK>>>(x, W_ih, W_hh, b_ih, b_hh, W_fc, b_fc,
                                 (float*)d_out, B);
}

// round 11
// speedup vs baseline: 1.2809x; 1.0134x over previous
#include <cuda_runtime.h>

#define T_STEPS 240
#define H       25
#define BLK     128
#define WPB     (BLK / 32)

typedef unsigned long long u64;

// ---------------------------------------------------------------------------
// Packed f32x2 helpers (Blackwell)
// ---------------------------------------------------------------------------
__device__ __forceinline__ u64 pack2(float lo, float hi) {
    u64 r;
    asm("mov.b64 %0, {%1, %2};" : "=l"(r) : "f"(lo), "f"(hi));
    return r;
}
__device__ __forceinline__ float unpack_sum(u64 v) {
    float lo, hi;
    asm("mov.b64 {%0, %1}, %2;" : "=f"(lo), "=f"(hi) : "l"(v));
    return lo + hi;
}
#define FFMA2(acc, h, w) \
    asm("fma.rn.f32x2 %0, %1, %2, %0;" : "+l"(acc) : "l"(h), "l"(w))

// ---------------------------------------------------------------------------
// Hardware tanh (single MUFU). Sigmoid gates use PRESCALED weights (x0.5
// folded into W/bias at load), so sigmoid(v) = fma(tanh(v_scaled), .5, .5)
// with no pre-multiply.
// ---------------------------------------------------------------------------
__device__ __forceinline__ float tanh_ap(float x) {
    float y;
    asm("tanh.approx.f32 %0, %1;" : "=f"(y) : "f"(x));
    return y;
}
__device__ __forceinline__ float sig_ps(float v_scaled) {  // v = 0.5*preact
    return fmaf(tanh_ap(v_scaled), 0.5f, 0.5f);
}

// Packed-k indices 0..12 (k pairs (0,1)..(24,25); k=25 padded to 0)
#define R13(M) M(0) M(1) M(2) M(3) M(4) M(5) M(6) M(7) M(8) M(9) M(10) M(11) M(12)

#define DECL_WP(Q) u64 wi##Q, wf##Q, wg##Q, wo##Q;

// Gate scale: i,f,o rows x0.5 (sigmoid prescale, exact); g row x1.
#define LOAD_WP(Q) {                                                          \
    const int k0 = 2 * (Q), k1 = 2 * (Q) + 1;                                 \
    float a, b;                                                               \
    a = (lv && k0 < H) ? 0.5f * __ldg(&W_hh[(0 * H + jc) * H + k0]) : 0.f;    \
    b = (lv && k1 < H) ? 0.5f * __ldg(&W_hh[(0 * H + jc) * H + k1]) : 0.f;    \
    wi##Q = pack2(a, b);                                                      \
    a = (lv && k0 < H) ? 0.5f * __ldg(&W_hh[(1 * H + jc) * H + k0]) : 0.f;    \
    b = (lv && k1 < H) ? 0.5f * __ldg(&W_hh[(1 * H + jc) * H + k1]) : 0.f;    \
    wf##Q = pack2(a, b);                                                      \
    a = (lv && k0 < H) ? __ldg(&W_hh[(2 * H + jc) * H + k0]) : 0.f;           \
    b = (lv && k1 < H) ? __ldg(&W_hh[(2 * H + jc) * H + k1]) : 0.f;           \
    wg##Q = pack2(a, b);                                                      \
    a = (lv && k0 < H) ? 0.5f * __ldg(&W_hh[(3 * H + jc) * H + k0]) : 0.f;    \
    b = (lv && k1 < H) ? 0.5f * __ldg(&W_hh[(3 * H + jc) * H + k1]) : 0.f;    \
    wo##Q = pack2(a, b);                                                      \
}

// 4 packed-gate FMAs for one packed h pair. S = batch (0/1), P = pair index.
#define GP(S, V, P)                                                           \
    FFMA2(ai##S, (V), wi##P); FFMA2(af##S, (V), wf##P);                       \
    FFMA2(ag##S, (V), wg##P); FFMA2(ao##S, (V), wo##P);

// One LSTM timestep for both batches. Bias + x-projection are folded into
// the accumulator INIT (low half), so the tail is just unpack_sum -> MUFU.
#define LSTM_STEP(B0, B1, XV0, XV1) do {                                      \
    if (lane < 28) { (B0)[lane] = h0; (B1)[lane] = h1; }                      \
    __syncwarp();                                                             \
    u64 ai0 = pack2(fmaf((XV0), wih_i, bias_i), 0.f);                         \
    u64 af0 = pack2(fmaf((XV0), wih_f, bias_f), 0.f);                         \
    u64 ag0 = pack2(fmaf((XV0), wih_g, bias_g), 0.f);                         \
    u64 ao0 = pack2(fmaf((XV0), wih_o, bias_o), 0.f);                         \
    u64 ai1 = pack2(fmaf((XV1), wih_i, bias_i), 0.f);                         \
    u64 af1 = pack2(fmaf((XV1), wih_f, bias_f), 0.f);                         \
    u64 ag1 = pack2(fmaf((XV1), wih_g, bias_g), 0.f);                         \
    u64 ao1 = pack2(fmaf((XV1), wih_o, bias_o), 0.f);                         \
    { ulonglong2 A = *reinterpret_cast<const ulonglong2*>((B0) + 0);          \
      ulonglong2 C = *reinterpret_cast<const ulonglong2*>((B1) + 0);          \
      GP(0, A.x, 0) GP(0, A.y, 1) GP(1, C.x, 0) GP(1, C.y, 1) }               \
    { ulonglong2 A = *reinterpret_cast<const ulonglong2*>((B0) + 4);          \
      ulonglong2 C = *reinterpret_cast<const ulonglong2*>((B1) + 4);          \
      GP(0, A.x, 2) GP(0, A.y, 3) GP(1, C.x, 2) GP(1, C.y, 3) }               \
    { ulonglong2 A = *reinterpret_cast<const ulonglong2*>((B0) + 8);          \
      ulonglong2 C = *reinterpret_cast<const ulonglong2*>((B1) + 8);          \
      GP(0, A.x, 4) GP(0, A.y, 5) GP(1, C.x, 4) GP(1, C.y, 5) }               \
    { ulonglong2 A = *reinterpret_cast<const ulonglong2*>((B0) + 12);         \
      ulonglong2 C = *reinterpret_cast<const ulonglong2*>((B1) + 12);         \
      GP(0, A.x, 6) GP(0, A.y, 7) GP(1, C.x, 6) GP(1, C.y, 7) }               \
    { ulonglong2 A = *reinterpret_cast<const ulonglong2*>((B0) + 16);         \
      ulonglong2 C = *reinterpret_cast<const ulonglong2*>((B1) + 16);         \
      GP(0, A.x, 8) GP(0, A.y, 9) GP(1, C.x, 8) GP(1, C.y, 9) }               \
    { ulonglong2 A = *reinterpret_cast<const ulonglong2*>((B0) + 20);         \
      ulonglong2 C = *reinterpret_cast<const ulonglong2*>((B1) + 20);         \
      GP(0, A.x, 10) GP(0, A.y, 11) GP(1, C.x, 10) GP(1, C.y, 11) }           \
    { u64 A = *reinterpret_cast<const u64*>((B0) + 24);                       \
      u64 C = *reinterpret_cast<const u64*>((B1) + 24);                       \
      GP(0, A, 12) GP(1, C, 12) }                                             \
    float ig = sig_ps(unpack_sum(ai0));                                       \
    float fg = sig_ps(unpack_sum(af0));                                       \
    float gg = tanh_ap(unpack_sum(ag0));                                      \
    float og = sig_ps(unpack_sum(ao0));                                       \
    c0 = fmaf(fg, c0, ig * gg);  h0 = og * tanh_ap(c0);                       \
    ig = sig_ps(unpack_sum(ai1));                                             \
    fg = sig_ps(unpack_sum(af1));                                             \
    gg = tanh_ap(unpack_sum(ag1));                                            \
    og = sig_ps(unpack_sum(ao1));                                             \
    c1 = fmaf(fg, c1, ig * gg);  h1 = og * tanh_ap(c1);                       \
} while (0)

__global__ void __launch_bounds__(BLK) lstm_kernel(
    const float* __restrict__ x,      // [B, T, 1]
    const float* __restrict__ W_ih,   // [4H, 1]
    const float* __restrict__ W_hh,   // [4H, H]
    const float* __restrict__ b_ih,   // [4H]
    const float* __restrict__ b_hh,   // [4H]
    const float* __restrict__ W_fc,   // [2, H]
    const float* __restrict__ b_fc,   // [2]
    float* __restrict__ out,          // [B, 2]
    int B)
{
    // h-broadcast buffers: [warp][parity][batch][28 units] (pads written as 0
    // by lanes 25-27, whose zero weights/biases keep their h exactly 0).
    __shared__ __align__(16) float hb[WPB][2][2][28];

    const int lane = threadIdx.x & 31;
    const int wIn  = threadIdx.x >> 5;
    const int warpGlobal = (blockIdx.x * BLK + threadIdx.x) >> 5;

    const bool lv = (lane < H);
    const int  jc = lv ? lane : (H - 1);

    int b0 = 2 * warpGlobal;
    int b1 = 2 * warpGlobal + 1;
    const bool v0 = (b0 < B), v1 = (b1 < B);
    if (!v0) b0 = B - 1;
    if (!v1) b1 = B - 1;

    // K-packed recurrent weights: 52 named u64 SSA values (cannot be demoted).
    R13(DECL_WP)
    R13(LOAD_WP)

    // x-projection weights & biases; i/f/o prescaled by 0.5 (exact).
    const float wih_i = lv ? 0.5f * __ldg(&W_ih[0 * H + jc]) : 0.f;
    const float wih_f = lv ? 0.5f * __ldg(&W_ih[1 * H + jc]) : 0.f;
    const float wih_g = lv ?        __ldg(&W_ih[2 * H + jc]) : 0.f;
    const float wih_o = lv ? 0.5f * __ldg(&W_ih[3 * H + jc]) : 0.f;
    const float bias_i = lv ? 0.5f * (__ldg(&b_ih[0 * H + jc]) + __ldg(&b_hh[0 * H + jc])) : 0.f;
    const float bias_f = lv ? 0.5f * (__ldg(&b_ih[1 * H + jc]) + __ldg(&b_hh[1 * H + jc])) : 0.f;
    const float bias_g = lv ?        (__ldg(&b_ih[2 * H + jc]) + __ldg(&b_hh[2 * H + jc])) : 0.f;
    const float bias_o = lv ? 0.5f * (__ldg(&b_ih[3 * H + jc]) + __ldg(&b_hh[3 * H + jc])) : 0.f;

    float* bA0 = &hb[wIn][0][0][0];
    float* bA1 = &hb[wIn][0][1][0];
    float* bB0 = &hb[wIn][1][0][0];
    float* bB1 = &hb[wIn][1][1][0];

    float h0 = 0.f, c0 = 0.f, h1 = 0.f, c1 = 0.f;

    const float4* xq0p = reinterpret_cast<const float4*>(x + (size_t)b0 * T_STEPS);
    const float4* xq1p = reinterpret_cast<const float4*>(x + (size_t)b1 * T_STEPS);

#pragma unroll 1
    for (int t4 = 0; t4 < T_STEPS / 4; t4++) {
        float4 xq0 = __ldg(xq0p + t4);   // warp-uniform broadcast loads
        float4 xq1 = __ldg(xq1p + t4);
        LSTM_STEP(bA0, bA1, xq0.x, xq1.x);
        LSTM_STEP(bB0, bB1, xq0.y, xq1.y);
        LSTM_STEP(bA0, bA1, xq0.z, xq1.z);
        LSTM_STEP(bB0, bB1, xq0.w, xq1.w);
    }

    // FC head: warp-reduce h . W_fc^T (idle lanes contribute h=0)
    const float wfc0 = lv ? __ldg(&W_fc[jc])     : 0.f;
    const float wfc1 = lv ? __ldg(&W_fc[H + jc]) : 0.f;
    float s00 = h0 * wfc0, s01 = h0 * wfc1;
    float s10 = h1 * wfc0, s11 = h1 * wfc1;
#pragma unroll
    for (int off = 16; off > 0; off >>= 1) {
        s00 += __shfl_xor_sync(0xffffffffu, s00, off);
        s01 += __shfl_xor_sync(0xffffffffu, s01, off);
        s10 += __shfl_xor_sync(0xffffffffu, s10, off);
        s11 += __shfl_xor_sync(0xffffffffu, s11, off);
    }
    if (lane == 0) {
        const float bf0 = __ldg(&b_fc[0]), bf1 = __ldg(&b_fc[1]);
        if (v0) {
            out[(size_t)b0 * 2 + 0] = s00 + bf0;
            out[(size_t)b0 * 2 + 1] = s01 + bf1;
        }
        if (v1) {
            out[(size_t)b1 * 2 + 0] = s10 + bf0;
            out[(size_t)b1 * 2 + 1] = s11 + bf1;
        }
    }
}

extern "C" void kernel_launch(void* const* d_in, const int* in_sizes, int n_in,
                              void* d_out, int out_size) {
    const float* x    = (const float*)d_in[0];
    const float* W_ih = (const float*)d_in[1];
    const float* W_hh = (const float*)d_in[2];
    const float* b_ih = (const float*)d_in[3];
    const float* b_hh = (const float*)d_in[4];
    const float* W_fc = (const float*)d_in[5];
    const float* b_fc = (const float*)d_in[6];

    int B = in_sizes[0] / T_STEPS;          // x is [B, T, 1]
    int warpsNeeded = (B + 1) / 2;          // 2 batches per warp
    int blocks      = (warpsNeeded * 32 + BLK - 1) / BLK;

    lstm_kernel<<<blocks, BLK>>>(x, W_ih, W_hh, b_ih, b_hh, W_fc, b_fc,
                                 (float*)d_out, B);
}

// round 13
// speedup vs baseline: 1.3084x; 1.0215x over previous
#include <cuda_runtime.h>

#define T_STEPS 240
#define H       25
#define BLK     128
#define WPB     (BLK / 32)

typedef unsigned long long u64;

// ---------------------------------------------------------------------------
// Packed f32x2 helpers (Blackwell)
// ---------------------------------------------------------------------------
__device__ __forceinline__ u64 pack2(float lo, float hi) {
    u64 r;
    asm("mov.b64 %0, {%1, %2};" : "=l"(r) : "f"(lo), "f"(hi));
    return r;
}
__device__ __forceinline__ float unpack_sum(u64 v) {
    float lo, hi;
    asm("mov.b64 {%0, %1}, %2;" : "=f"(lo), "=f"(hi) : "l"(v));
    return lo + hi;
}
#define FFMA2(acc, h, w) \
    asm("fma.rn.f32x2 %0, %1, %2, %0;" : "+l"(acc) : "l"(h), "l"(w))

// ---------------------------------------------------------------------------
// Hardware tanh (single MUFU). Sigmoid gates use PRESCALED weights (x0.5
// folded into W/bias at load): sigmoid(v) = fma(tanh(v_scaled), .5, .5).
// ---------------------------------------------------------------------------
__device__ __forceinline__ float tanh_ap(float x) {
    float y;
    asm("tanh.approx.f32 %0, %1;" : "=f"(y) : "f"(x));
    return y;
}
__device__ __forceinline__ float sig_ps(float v_scaled) {
    return fmaf(tanh_ap(v_scaled), 0.5f, 0.5f);
}

// Packed-k indices 0..12 (k pairs (0,1)..(24,25); k=25 padded to 0)
#define R13(M) M(0) M(1) M(2) M(3) M(4) M(5) M(6) M(7) M(8) M(9) M(10) M(11) M(12)

#define DECL_WP(Q) u64 wi##Q, wf##Q, wg##Q, wo##Q;

// Gate scale: i,f,o rows x0.5 (sigmoid prescale, exact); g row x1.
#define LOAD_WP(Q) {                                                          \
    const int k0 = 2 * (Q), k1 = 2 * (Q) + 1;                                 \
    float a, b;                                                               \
    a = (lv && k0 < H) ? 0.5f * __ldg(&W_hh[(0 * H + jc) * H + k0]) : 0.f;    \
    b = (lv && k1 < H) ? 0.5f * __ldg(&W_hh[(0 * H + jc) * H + k1]) : 0.f;    \
    wi##Q = pack2(a, b);                                                      \
    a = (lv && k0 < H) ? 0.5f * __ldg(&W_hh[(1 * H + jc) * H + k0]) : 0.f;    \
    b = (lv && k1 < H) ? 0.5f * __ldg(&W_hh[(1 * H + jc) * H + k1]) : 0.f;    \
    wf##Q = pack2(a, b);                                                      \
    a = (lv && k0 < H) ? __ldg(&W_hh[(2 * H + jc) * H + k0]) : 0.f;           \
    b = (lv && k1 < H) ? __ldg(&W_hh[(2 * H + jc) * H + k1]) : 0.f;           \
    wg##Q = pack2(a, b);                                                      \
    a = (lv && k0 < H) ? 0.5f * __ldg(&W_hh[(3 * H + jc) * H + k0]) : 0.f;    \
    b = (lv && k1 < H) ? 0.5f * __ldg(&W_hh[(3 * H + jc) * H + k1]) : 0.f;    \
    wo##Q = pack2(a, b);                                                      \
}

// Full 13-pair MAC for one accumulator from preloaded h regs (A0..A5 u64x2,
// A6 u64). Same accumulation order as before -> bitwise-identical results.
#define MAC1(acc, W, A0, A1, A2, A3, A4, A5, A6)                              \
    FFMA2(acc, (A0).x, W##0);  FFMA2(acc, (A0).y, W##1);                      \
    FFMA2(acc, (A1).x, W##2);  FFMA2(acc, (A1).y, W##3);                      \
    FFMA2(acc, (A2).x, W##4);  FFMA2(acc, (A2).y, W##5);                      \
    FFMA2(acc, (A3).x, W##6);  FFMA2(acc, (A3).y, W##7);                      \
    FFMA2(acc, (A4).x, W##8);  FFMA2(acc, (A4).y, W##9);                      \
    FFMA2(acc, (A5).x, W##10); FFMA2(acc, (A5).y, W##11);                     \
    FFMA2(acc, (A6),   W##12);

// One LSTM timestep for both batches. KEY SCHEDULING CHANGE vs R11: the
// g-gate accumulators run FIRST and their tanh MUFUs are launched before
// the 78 i/f/o FFMA2s, which then hide the 16-cycle MUFU latency. The
// per-accumulator arithmetic order is unchanged (bitwise-identical output).
#define LSTM_STEP(B0, B1, XV0, XV1) do {                                      \
    if (lane < 28) { (B0)[lane] = h0; (B1)[lane] = h1; }                      \
    __syncwarp();                                                             \
    ulonglong2 A0 = *reinterpret_cast<const ulonglong2*>((B0) + 0);           \
    ulonglong2 A1 = *reinterpret_cast<const ulonglong2*>((B0) + 4);           \
    ulonglong2 A2 = *reinterpret_cast<const ulonglong2*>((B0) + 8);           \
    ulonglong2 A3 = *reinterpret_cast<const ulonglong2*>((B0) + 12);          \
    ulonglong2 A4 = *reinterpret_cast<const ulonglong2*>((B0) + 16);          \
    ulonglong2 A5 = *reinterpret_cast<const ulonglong2*>((B0) + 20);          \
    u64        A6 = *reinterpret_cast<const u64*>((B0) + 24);                 \
    ulonglong2 C0 = *reinterpret_cast<const ulonglong2*>((B1) + 0);           \
    ulonglong2 C1 = *reinterpret_cast<const ulonglong2*>((B1) + 4);           \
    ulonglong2 C2 = *reinterpret_cast<const ulonglong2*>((B1) + 8);           \
    ulonglong2 C3 = *reinterpret_cast<const ulonglong2*>((B1) + 12);          \
    ulonglong2 C4 = *reinterpret_cast<const ulonglong2*>((B1) + 16);          \
    ulonglong2 C5 = *reinterpret_cast<const ulonglong2*>((B1) + 20);          \
    u64        C6 = *reinterpret_cast<const u64*>((B1) + 24);                 \
    /* g-gate first: feeds the longest tail chain */                          \
    u64 ag0 = pack2(fmaf((XV0), wih_g, bias_g), 0.f);                         \
    u64 ag1 = pack2(fmaf((XV1), wih_g, bias_g), 0.f);                         \
    MAC1(ag0, wg, A0, A1, A2, A3, A4, A5, A6)                                 \
    MAC1(ag1, wg, C0, C1, C2, C3, C4, C5, C6)                                 \
    float gg0 = tanh_ap(unpack_sum(ag0));   /* MUFU in flight ... */          \
    float gg1 = tanh_ap(unpack_sum(ag1));                                     \
    /* ... while i/f/o MACs execute */                                        \
    u64 ai0 = pack2(fmaf((XV0), wih_i, bias_i), 0.f);                         \
    u64 af0 = pack2(fmaf((XV0), wih_f, bias_f), 0.f);                         \
    u64 ao0 = pack2(fmaf((XV0), wih_o, bias_o), 0.f);                         \
    u64 ai1 = pack2(fmaf((XV1), wih_i, bias_i), 0.f);                         \
    u64 af1 = pack2(fmaf((XV1), wih_f, bias_f), 0.f);                         \
    u64 ao1 = pack2(fmaf((XV1), wih_o, bias_o), 0.f);                         \
    MAC1(ai0, wi, A0, A1, A2, A3, A4, A5, A6)                                 \
    MAC1(af0, wf, A0, A1, A2, A3, A4, A5, A6)                                 \
    MAC1(ao0, wo, A0, A1, A2, A3, A4, A5, A6)                                 \
    MAC1(ai1, wi, C0, C1, C2, C3, C4, C5, C6)                                 \
    MAC1(af1, wf, C0, C1, C2, C3, C4, C5, C6)                                 \
    MAC1(ao1, wo, C0, C1, C2, C3, C4, C5, C6)                                 \
    float ig = sig_ps(unpack_sum(ai0));                                       \
    float fg = sig_ps(unpack_sum(af0));                                       \
    float og = sig_ps(unpack_sum(ao0));                                       \
    c0 = fmaf(fg, c0, ig * gg0);  h0 = og * tanh_ap(c0);                      \
    ig = sig_ps(unpack_sum(ai1));                                             \
    fg = sig_ps(unpack_sum(af1));                                             \
    og = sig_ps(unpack_sum(ao1));                                             \
    c1 = fmaf(fg, c1, ig * gg1);  h1 = og * tanh_ap(c1);                      \
} while (0)

__global__ void __launch_bounds__(BLK) lstm_kernel(
    const float* __restrict__ x,      // [B, T, 1]
    const float* __restrict__ W_ih,   // [4H, 1]
    const float* __restrict__ W_hh,   // [4H, H]
    const float* __restrict__ b_ih,   // [4H]
    const float* __restrict__ b_hh,   // [4H]
    const float* __restrict__ W_fc,   // [2, H]
    const float* __restrict__ b_fc,   // [2]
    float* __restrict__ out,          // [B, 2]
    int B)
{
    // h-broadcast buffers: [warp][parity][batch][28 units] (pads written as 0
    // by lanes 25-27, whose zero weights/biases keep their h exactly 0).
    __shared__ __align__(16) float hb[WPB][2][2][28];

    const int lane = threadIdx.x & 31;
    const int wIn  = threadIdx.x >> 5;
    const int warpGlobal = (blockIdx.x * BLK + threadIdx.x) >> 5;

    const bool lv = (lane < H);
    const int  jc = lv ? lane : (H - 1);

    int b0 = 2 * warpGlobal;
    int b1 = 2 * warpGlobal + 1;
    const bool v0 = (b0 < B), v1 = (b1 < B);
    if (!v0) b0 = B - 1;
    if (!v1) b1 = B - 1;

    // K-packed recurrent weights: 52 named u64 SSA values (cannot be demoted).
    R13(DECL_WP)
    R13(LOAD_WP)

    // x-projection weights & biases; i/f/o prescaled by 0.5 (exact).
    const float wih_i = lv ? 0.5f * __ldg(&W_ih[0 * H + jc]) : 0.f;
    const float wih_f = lv ? 0.5f * __ldg(&W_ih[1 * H + jc]) : 0.f;
    const float wih_g = lv ?        __ldg(&W_ih[2 * H + jc]) : 0.f;
    const float wih_o = lv ? 0.5f * __ldg(&W_ih[3 * H + jc]) : 0.f;
    const float bias_i = lv ? 0.5f * (__ldg(&b_ih[0 * H + jc]) + __ldg(&b_hh[0 * H + jc])) : 0.f;
    const float bias_f = lv ? 0.5f * (__ldg(&b_ih[1 * H + jc]) + __ldg(&b_hh[1 * H + jc])) : 0.f;
    const float bias_g = lv ?        (__ldg(&b_ih[2 * H + jc]) + __ldg(&b_hh[2 * H + jc])) : 0.f;
    const float bias_o = lv ? 0.5f * (__ldg(&b_ih[3 * H + jc]) + __ldg(&b_hh[3 * H + jc])) : 0.f;

    float* bA0 = &hb[wIn][0][0][0];
    float* bA1 = &hb[wIn][0][1][0];
    float* bB0 = &hb[wIn][1][0][0];
    float* bB1 = &hb[wIn][1][1][0];

    float h0 = 0.f, c0 = 0.f, h1 = 0.f, c1 = 0.f;

    const float4* xq0p = reinterpret_cast<const float4*>(x + (size_t)b0 * T_STEPS);
    const float4* xq1p = reinterpret_cast<const float4*>(x + (size_t)b1 * T_STEPS);

#pragma unroll 1
    for (int t4 = 0; t4 < T_STEPS / 4; t4++) {
        float4 xq0 = __ldg(xq0p + t4);   // warp-uniform broadcast loads
        float4 xq1 = __ldg(xq1p + t4);
        LSTM_STEP(bA0, bA1, xq0.x, xq1.x);
        LSTM_STEP(bB0, bB1, xq0.y, xq1.y);
        LSTM_STEP(bA0, bA1, xq0.z, xq1.z);
        LSTM_STEP(bB0, bB1, xq0.w, xq1.w);
    }

    // FC head: warp-reduce h . W_fc^T (idle lanes contribute h=0)
    const float wfc0 = lv ? __ldg(&W_fc[jc])     : 0.f;
    const float wfc1 = lv ? __ldg(&W_fc[H + jc]) : 0.f;
    float s00 = h0 * wfc0, s01 = h0 * wfc1;
    float s10 = h1 * wfc0, s11 = h1 * wfc1;
#pragma unroll
    for (int off = 16; off > 0; off >>= 1) {
        s00 += __shfl_xor_sync(0xffffffffu, s00, off);
        s01 += __shfl_xor_sync(0xffffffffu, s01, off);
        s10 += __shfl_xor_sync(0xffffffffu, s10, off);
        s11 += __shfl_xor_sync(0xffffffffu, s11, off);
    }
    if (lane == 0) {
        const float bf0 = __ldg(&b_fc[0]), bf1 = __ldg(&b_fc[1]);
        if (v0) {
            out[(size_t)b0 * 2 + 0] = s00 + bf0;
            out[(size_t)b0 * 2 + 1] = s01 + bf1;
        }
        if (v1) {
            out[(size_t)b1 * 2 + 0] = s10 + bf0;
            out[(size_t)b1 * 2 + 1] = s11 + bf1;
        }
    }
}

extern "C" void kernel_launch(void* const* d_in, const int* in_sizes, int n_in,
                              void* d_out, int out_size) {
    const float* x    = (const float*)d_in[0];
    const float* W_ih = (const float*)d_in[1];
    const float* W_hh = (const float*)d_in[2];
    const float* b_ih = (const float*)d_in[3];
    const float* b_hh = (const float*)d_in[4];
    const float* W_fc = (const float*)d_in[5];
    const float* b_fc = (const float*)d_in[6];

    int B = in_sizes[0] / T_STEPS;          // x is [B, T, 1]
    int warpsNeeded = (B + 1) / 2;          // 2 batches per warp
    int blocks      = (warpsNeeded * 32 + BLK - 1) / BLK;

    lstm_kernel<<<blocks, BLK>>>(x, W_ih, W_hh, b_ih, b_hh, W_fc, b_fc,
                                 (float*)d_out, B);
}